// round 12
// baseline (speedup 1.0000x reference)
#include <cuda_runtime.h>
#include <cstdint>

#define Bz 64
#define Sz 512
#define Hz 1024
#define Tz 17
#define ROWS (Bz * Sz)   // 32768

// ---------------------------------------------------------------------------
// Kernel 1: feats[r][t] = dot(x[r,:], W[t,:]) + b[t]
// R1 version, measured 53.8us. Unchanged this round.
// ---------------------------------------------------------------------------
__global__ __launch_bounds__(256) void crf_gemm_kernel(
    const float* __restrict__ x, const float* __restrict__ W,
    const float* __restrict__ bias, float* __restrict__ feats) {
  __shared__ float Wsh[Tz * 512];  // 34816 B

  const int tid = threadIdx.x;
  const int warp = tid >> 5;
  const int lane = tid & 31;
  const int group = lane >> 2;
  const int sub = lane & 3;

  const int rowbase = blockIdx.x * 128 + warp * 16 + group * 2;
  const float* x0 = x + (size_t)rowbase * Hz;
  const float* x1 = x0 + Hz;

  float acc0[Tz], acc1[Tz];
#pragma unroll
  for (int t = 0; t < Tz; t++) { acc0[t] = 0.f; acc1[t] = 0.f; }

  for (int half = 0; half < 2; half++) {
    __syncthreads();
    for (int i = tid * 4; i < Tz * 512; i += 1024) {
      int t = i >> 9;
      int hh = i & 511;
      *(float4*)&Wsh[i] = *(const float4*)&W[t * Hz + half * 512 + hh];
    }
    __syncthreads();

    const float* xh0 = x0 + half * 512;
    const float* xh1 = x1 + half * 512;
#pragma unroll 2
    for (int h0 = 0; h0 < 512; h0 += 16) {
      const int h = h0 + sub * 4;
      const float4 xa = *(const float4*)(xh0 + h);
      const float4 xb = *(const float4*)(xh1 + h);
#pragma unroll
      for (int t = 0; t < Tz; t++) {
        const float4 wv = *(const float4*)&Wsh[t * 512 + h];
        acc0[t] += xa.x * wv.x + xa.y * wv.y + xa.z * wv.z + xa.w * wv.w;
        acc1[t] += xb.x * wv.x + xb.y * wv.y + xb.z * wv.z + xb.w * wv.w;
      }
    }
  }

#pragma unroll
  for (int t = 0; t < Tz; t++) {
    acc0[t] += __shfl_xor_sync(0xffffffffu, acc0[t], 1);
    acc0[t] += __shfl_xor_sync(0xffffffffu, acc0[t], 2);
    acc1[t] += __shfl_xor_sync(0xffffffffu, acc1[t], 1);
    acc1[t] += __shfl_xor_sync(0xffffffffu, acc1[t], 2);
  }
  if (sub == 0) {
#pragma unroll
    for (int t = 0; t < Tz; t++) {
      feats[(size_t)rowbase * Tz + t] = acc0[t] + bias[t];
      feats[(size_t)(rowbase + 1) * Tz + t] = acc1[t] + bias[t];
    }
  }
}

// ---------------------------------------------------------------------------
// Fused max + first-argmax, depth-5 left-biased tournament with FLOAT
// indices. Float ternaries compile to FSETP+FSEL: the predicate is consumed
// as DATA (lat 4) instead of as a guard (lat 13), removing the ~65-cyc
// serial predicate chain measured in R8. Left bias (a >= b keeps left)
// == jnp.argmax first-max tie-break.
// ---------------------------------------------------------------------------
__device__ __forceinline__ void tourney17f(const float* __restrict__ c,
                                           float& m, float& idxf) {
  float v0[8], i0[8];
#pragma unroll
  for (int k = 0; k < 8; k++) {
    const float a = c[2 * k], b = c[2 * k + 1];
    v0[k] = fmaxf(a, b);
    i0[k] = (a >= b) ? (float)(2 * k) : (float)(2 * k + 1);
  }
  float v1[4], i1[4];
#pragma unroll
  for (int k = 0; k < 4; k++) {
    v1[k] = fmaxf(v0[2 * k], v0[2 * k + 1]);
    i1[k] = (v0[2 * k] >= v0[2 * k + 1]) ? i0[2 * k] : i0[2 * k + 1];
  }
  float v2[2], i2[2];
#pragma unroll
  for (int k = 0; k < 2; k++) {
    v2[k] = fmaxf(v1[2 * k], v1[2 * k + 1]);
    i2[k] = (v1[2 * k] >= v1[2 * k + 1]) ? i1[2 * k] : i1[2 * k + 1];
  }
  const float v3 = fmaxf(v2[0], v2[1]);
  const float i3 = (v2[0] >= v2[1]) ? i2[0] : i2[1];
  m = fmaxf(v3, c[16]);
  idxf = (v3 >= c[16]) ? i3 : 16.0f;
}

// ---------------------------------------------------------------------------
// Kernel 2: Viterbi, monolithic. 64 blocks; warp 0 runs the recurrence,
// lane t owns tag t. Only steps s = 1..nwords-1 run (masked steps are
// identity in the reference; padded tags are zeroed anyway).
// ---------------------------------------------------------------------------
__global__ __launch_bounds__(128) void crf_viterbi_kernel(
    const float* __restrict__ feats, const float* __restrict__ trans,
    const float* __restrict__ start_t, const float* __restrict__ end_t,
    const int* __restrict__ nwords, float* __restrict__ tags_out) {
  __shared__ float fsh[Sz * Tz];           // 34816 B
  __shared__ unsigned char bp_sh[Sz * Tz]; // 8704 B

  const int b = blockIdx.x;
  const int tid = threadIdx.x;
  const float* fb = feats + (size_t)b * Sz * Tz;

  for (int i = tid * 4; i < Sz * Tz; i += 512)
    *(float4*)&fsh[i] = *(const float4*)&fb[i];

  const int nw = nwords[b];
  __syncthreads();

  if (tid < 32) {
    const int t = tid;
    const int tc = (t < Tz) ? t : (Tz - 1);
    float tcol[Tz];
#pragma unroll
    for (int j = 0; j < Tz; j++) tcol[j] = trans[j * Tz + tc];

    float score = start_t[tc] + fsh[tc];
    const float* frow = fsh + Tz;
    unsigned char* bprow = bp_sh + Tz;

    for (int s = 1; s < nw; s++) {
      float c[Tz];
#pragma unroll
      for (int j = 0; j < Tz; j++)
        c[j] = __shfl_sync(0xffffffffu, score, j) + tcol[j];
      float m, bpf;
      tourney17f(c, m, bpf);
      score = m + frow[tc];
      if (t < Tz) bprow[t] = (unsigned char)(int)bpf;
      frow += Tz;
      bprow += Tz;
    }

    const float fin = score + end_t[tc];
    float fc[Tz];
#pragma unroll
    for (int j = 0; j < Tz; j++) fc[j] = __shfl_sync(0xffffffffu, fin, j);
    float fm, ltf;
    tourney17f(fc, fm, ltf);
    const int last_tag = (int)ltf;

    if (t == 0) {
      float* out = tags_out + (size_t)b * Sz;
      int tag = last_tag;
      out[nw - 1] = (float)tag;
      const unsigned char* bpr = bp_sh + (size_t)(nw - 1) * Tz;
      for (int s = nw - 1; s >= 1; s--) {
        tag = bpr[tag];
        bpr -= Tz;
        out[s - 1] = (float)tag;
      }
    }
  }

  // Zero the masked tail (disjoint from backtrack writes).
  for (int s = nw + tid; s < Sz; s += blockDim.x)
    tags_out[(size_t)b * Sz + s] = 0.0f;
}

// ---------------------------------------------------------------------------
// Inputs: x, W, b, transitions, start_trans, end_trans, nwords
// Output: [padded_tags (64*512) | feats (64*512*17)] as float32.
// ---------------------------------------------------------------------------
extern "C" void kernel_launch(void* const* d_in, const int* in_sizes, int n_in,
                              void* d_out, int out_size) {
  const float* x = (const float*)d_in[0];
  const float* W = (const float*)d_in[1];
  const float* bias = (const float*)d_in[2];
  const float* trans = (const float*)d_in[3];
  const float* start_t = (const float*)d_in[4];
  const float* end_t = (const float*)d_in[5];
  const int* nwords = (const int*)d_in[6];

  float* tags_out = (float*)d_out;
  float* feats = (float*)d_out + (size_t)Bz * Sz;

  crf_gemm_kernel<<<ROWS / 128, 256>>>(x, W, bias, feats);
  crf_viterbi_kernel<<<Bz, 128>>>(feats, trans, start_t, end_t, nwords, tags_out);
}

// round 13
// speedup vs baseline: 1.1172x; 1.1172x over previous
#include <cuda_runtime.h>
#include <cstdint>

#define Bz 64
#define Sz 512
#define Hz 1024
#define Tz 17
#define ROWS (Bz * Sz)   // 32768

// ---------------------------------------------------------------------------
// Kernel 1: feats[r][t] = dot(x[r,:], W[t,:]) + b[t]
// R1 version, measured 53.8us. Unchanged.
// ---------------------------------------------------------------------------
__global__ __launch_bounds__(256) void crf_gemm_kernel(
    const float* __restrict__ x, const float* __restrict__ W,
    const float* __restrict__ bias, float* __restrict__ feats) {
  __shared__ float Wsh[Tz * 512];  // 34816 B

  const int tid = threadIdx.x;
  const int warp = tid >> 5;
  const int lane = tid & 31;
  const int group = lane >> 2;
  const int sub = lane & 3;

  const int rowbase = blockIdx.x * 128 + warp * 16 + group * 2;
  const float* x0 = x + (size_t)rowbase * Hz;
  const float* x1 = x0 + Hz;

  float acc0[Tz], acc1[Tz];
#pragma unroll
  for (int t = 0; t < Tz; t++) { acc0[t] = 0.f; acc1[t] = 0.f; }

  for (int half = 0; half < 2; half++) {
    __syncthreads();
    for (int i = tid * 4; i < Tz * 512; i += 1024) {
      int t = i >> 9;
      int hh = i & 511;
      *(float4*)&Wsh[i] = *(const float4*)&W[t * Hz + half * 512 + hh];
    }
    __syncthreads();

    const float* xh0 = x0 + half * 512;
    const float* xh1 = x1 + half * 512;
#pragma unroll 2
    for (int h0 = 0; h0 < 512; h0 += 16) {
      const int h = h0 + sub * 4;
      const float4 xa = *(const float4*)(xh0 + h);
      const float4 xb = *(const float4*)(xh1 + h);
#pragma unroll
      for (int t = 0; t < Tz; t++) {
        const float4 wv = *(const float4*)&Wsh[t * 512 + h];
        acc0[t] += xa.x * wv.x + xa.y * wv.y + xa.z * wv.z + xa.w * wv.w;
        acc1[t] += xb.x * wv.x + xb.y * wv.y + xb.z * wv.z + xb.w * wv.w;
      }
    }
  }

#pragma unroll
  for (int t = 0; t < Tz; t++) {
    acc0[t] += __shfl_xor_sync(0xffffffffu, acc0[t], 1);
    acc0[t] += __shfl_xor_sync(0xffffffffu, acc0[t], 2);
    acc1[t] += __shfl_xor_sync(0xffffffffu, acc1[t], 1);
    acc1[t] += __shfl_xor_sync(0xffffffffu, acc1[t], 2);
  }
  if (sub == 0) {
#pragma unroll
    for (int t = 0; t < Tz; t++) {
      feats[(size_t)rowbase * Tz + t] = acc0[t] + bias[t];
      feats[(size_t)(rowbase + 1) * Tz + t] = acc1[t] + bias[t];
    }
  }
}

// ---------------------------------------------------------------------------
// Value-only max over 17 (depth-5 tree, no index bookkeeping).
// ---------------------------------------------------------------------------
__device__ __forceinline__ float max17(const float* c) {
  float a = fmaxf(fmaxf(fmaxf(c[0], c[1]), fmaxf(c[2], c[3])),
                  fmaxf(fmaxf(c[4], c[5]), fmaxf(c[6], c[7])));
  float b = fmaxf(fmaxf(fmaxf(c[8], c[9]), fmaxf(c[10], c[11])),
                  fmaxf(fmaxf(c[12], c[13]), fmaxf(c[14], c[15])));
  return fmaxf(fmaxf(a, b), c[16]);
}

// ---------------------------------------------------------------------------
// Fused max + first-argmax, depth-5 left-biased tournament (R8 int version,
// measured best). Left bias (a >= b keeps left) == jnp.argmax tie-break.
// ---------------------------------------------------------------------------
__device__ __forceinline__ void tourney17(const float* __restrict__ c,
                                          float& m, int& idx) {
  float v0[8]; int i0[8];
#pragma unroll
  for (int k = 0; k < 8; k++) {
    const float a = c[2 * k], b = c[2 * k + 1];
    v0[k] = fmaxf(a, b);
    i0[k] = (a >= b) ? (2 * k) : (2 * k + 1);
  }
  float v1[4]; int i1[4];
#pragma unroll
  for (int k = 0; k < 4; k++) {
    v1[k] = fmaxf(v0[2 * k], v0[2 * k + 1]);
    i1[k] = (v0[2 * k] >= v0[2 * k + 1]) ? i0[2 * k] : i0[2 * k + 1];
  }
  float v2[2]; int i2[2];
#pragma unroll
  for (int k = 0; k < 2; k++) {
    v2[k] = fmaxf(v1[2 * k], v1[2 * k + 1]);
    i2[k] = (v1[2 * k] >= v1[2 * k + 1]) ? i1[2 * k] : i1[2 * k + 1];
  }
  const float v3 = fmaxf(v2[0], v2[1]);
  const int i3 = (v2[0] >= v2[1]) ? i2[0] : i2[1];
  m = fmaxf(v3, c[16]);
  idx = (v3 >= c[16]) ? i3 : 16;
}

// ---------------------------------------------------------------------------
// Kernel 2: Viterbi in 3 phases, one block per batch.
//  Phase 1 (warp 0, serial): max-only forward recurrence. Score row s
//    overwrites feats row s in fsh (feats row s is dead after step s).
//  Phase 2 (all 4 warps, parallel over s): bp[s][t] =
//    argfirst_j(score[s-1][j] + T[j][t]) recomputed from the score history.
//  Phase 3 (warp 0): final argmax + serial u8 chase; other threads zero tail.
// Masked steps (s >= nwords) are identity in the reference -> skipped.
// ---------------------------------------------------------------------------
__global__ __launch_bounds__(128) void crf_viterbi_kernel(
    const float* __restrict__ feats, const float* __restrict__ trans,
    const float* __restrict__ start_t, const float* __restrict__ end_t,
    const int* __restrict__ nwords, float* __restrict__ tags_out) {
  __shared__ float fsh[Sz * Tz];           // feats, then score history
  __shared__ unsigned char bp_sh[Sz * Tz]; // backpointers

  const int b = blockIdx.x;
  const int tid = threadIdx.x;
  const int warp = tid >> 5;
  const int lane = tid & 31;
  const float* fb = feats + (size_t)b * Sz * Tz;

  for (int i = tid * 4; i < Sz * Tz; i += 512)
    *(float4*)&fsh[i] = *(const float4*)&fb[i];

  const int nw = nwords[b];
  const int tc = (lane < Tz) ? lane : (Tz - 1);
  float tcol[Tz];
#pragma unroll
  for (int j = 0; j < Tz; j++) tcol[j] = trans[j * Tz + tc];
  __syncthreads();

  // ---- Phase 1: serial forward (max only), warp 0 ----
  if (tid < 32) {
    float score = start_t[tc] + fsh[tc];
    fsh[tc] = score;  // score row 0 (lanes 17-31 rewrite [16] with same value)
    float* frow = fsh + Tz;
    for (int s = 1; s < nw; s++) {
      float c[Tz];
#pragma unroll
      for (int j = 0; j < Tz; j++)
        c[j] = __shfl_sync(0xffffffffu, score, j) + tcol[j];
      score = max17(c) + frow[tc];
      frow[tc] = score;  // overwrite feats row s with score row s
      frow += Tz;
    }
  }
  __syncthreads();

  // ---- Phase 2: backpointers, parallel over s across 4 warps ----
  for (int s = 1 + warp; s < nw; s += 4) {
    const float* srow = fsh + (size_t)(s - 1) * Tz;
    float c[Tz];
#pragma unroll
    for (int j = 0; j < Tz; j++) c[j] = srow[j] + tcol[j];  // broadcast LDS
    float m; int bp;
    tourney17(c, m, bp);
    if (lane < Tz) bp_sh[s * Tz + lane] = (unsigned char)bp;
  }
  __syncthreads();

  // ---- Phase 3: final argmax + chase (warp 0), tail zero (all) ----
  if (tid < 32) {
    const float fin = fsh[(size_t)(nw - 1) * Tz + tc] + end_t[tc];
    float fc[Tz];
#pragma unroll
    for (int j = 0; j < Tz; j++) fc[j] = __shfl_sync(0xffffffffu, fin, j);
    float fm; int last_tag;
    tourney17(fc, fm, last_tag);

    if (lane == 0) {
      float* out = tags_out + (size_t)b * Sz;
      int tag = last_tag;
      out[nw - 1] = (float)tag;
      const unsigned char* bpr = bp_sh + (size_t)(nw - 1) * Tz;
      for (int s = nw - 1; s >= 1; s--) {
        tag = bpr[tag];
        bpr -= Tz;
        out[s - 1] = (float)tag;
      }
    }
  }

  for (int s = nw + tid; s < Sz; s += blockDim.x)
    tags_out[(size_t)b * Sz + s] = 0.0f;
}

// ---------------------------------------------------------------------------
// Inputs: x, W, b, transitions, start_trans, end_trans, nwords
// Output: [padded_tags (64*512) | feats (64*512*17)] as float32.
// ---------------------------------------------------------------------------
extern "C" void kernel_launch(void* const* d_in, const int* in_sizes, int n_in,
                              void* d_out, int out_size) {
  const float* x = (const float*)d_in[0];
  const float* W = (const float*)d_in[1];
  const float* bias = (const float*)d_in[2];
  const float* trans = (const float*)d_in[3];
  const float* start_t = (const float*)d_in[4];
  const float* end_t = (const float*)d_in[5];
  const int* nwords = (const int*)d_in[6];

  float* tags_out = (float*)d_out;
  float* feats = (float*)d_out + (size_t)Bz * Sz;

  crf_gemm_kernel<<<ROWS / 128, 256>>>(x, W, bias, feats);
  crf_viterbi_kernel<<<Bz, 128>>>(feats, trans, start_t, end_t, nwords, tags_out);
}